// round 6
// baseline (speedup 1.0000x reference)
#include <cuda_runtime.h>

// CostVolumeCorrelationLayer: B=8, H=W=128, C=128, maxDisp=4 -> 81 displacements
// out[b,y,x, dy*9+dx] = leaky_relu( mean_c( F1[b,y,x,c] * F2pad[b,y+dy,x+dx,c] ), 0.1 )
//
// Round-5: channel-pair f32x2 packing.
//  - acc[px][dx] holds (sum over even ch, sum over odd ch); final = lo+hi.
//  - smem rows = channel PAIRS, elements = px as float2 (8B). Every FFMA2
//    operand is a natural 8B half of an LDS.128 -> zero re-pairing MOVs.
//  - row stride RLEN=138 f2 (1104B, 16B aligned); XOR swizzle on f4 index
//    sigma(i) = i ^ ((i>>3)&1) makes both the stride-2-f4 compute loads and
//    the fill STS.64 conflict-free.
//  - CCH=32 channels/chunk, 4 chunks, monolithic fill/compute phases.

#define BB 8
#define HH 128
#define WW 128
#define CC_TOT 128
#define KDISP 81

#define CCH 32
#define NCHUNK (CC_TOT / CCH)    // 4
#define NCP (CCH / 2)            // 16 channel-pair rows per chunk
#define NTHREADS 576             // 18 warps = (row 0..1, dy 0..8)
#define ROWS_PER_CTA 2
#define F2ROWS 10

#define RLEN 138                 // float2 per row; 138*8=1104B, 16B-aligned rows
#define F2_ULL (F2ROWS * NCP * RLEN)          // 22080 ull
#define F1_ULL (ROWS_PER_CTA * NCP * RLEN)    // 4416 ull
#define SMEM_BYTES ((F2_ULL + F1_ULL) * 8)    // 211968 B

using ull = unsigned long long;

__device__ __forceinline__ void ffma2(ull &acc, ull a, ull b) {
    asm("fma.rn.f32x2 %0, %1, %2, %0;" : "+l"(acc) : "l"(a), "l"(b));
}
__device__ __forceinline__ int swz4(int i) { return i ^ ((i >> 3) & 1); }
// element (f2) position for pixel-index pxi within a row
__device__ __forceinline__ int spos(int pxi) { return swz4(pxi >> 1) * 2 + (pxi & 1); }

__global__ __launch_bounds__(NTHREADS, 1)
void corr_kernel(const float* __restrict__ F1,
                 const float* __restrict__ F2,
                 float* __restrict__ out)
{
    extern __shared__ ull smemu[];
    ull* F2u = smemu;            // [10][NCP][RLEN]
    ull* F1u = smemu + F2_ULL;   // [2][NCP][RLEN]

    const int y0  = blockIdx.x * 2;
    const int b   = blockIdx.y;
    const int tid = threadIdx.x;
    const int w   = tid >> 5;
    const int g   = tid & 31;
    const int row = (w >= 9) ? 1 : 0;
    const int dy  = w - 9 * row;

    // per-lane swizzled f4 (ulonglong2) load indices: f4 2g+j, j=0..5
    int vj[6];
#pragma unroll
    for (int j = 0; j < 6; j++) vj[j] = swz4(2 * g + j);

    ull acc[4][9];
#pragma unroll
    for (int i = 0; i < 4; i++)
#pragma unroll
        for (int dx = 0; dx < 9; dx++) acc[i][dx] = 0ull;

    for (int ck = 0; ck < NCHUNK; ck++) {
        const int c0 = ck * CCH;
        __syncthreads();   // previous chunk's compute done before refill

        // ---- F2 fill: LDG.128 (4 ch @ 1 px), coalesced; 2x STS.64 to cpair rows ----
        // q -> xi=q&3 (px-in-block), cq=(q>>2)&7 (channel quad), rb=q>>5 -> (r, xb)
        for (int q = tid; q < F2ROWS * 136 * 8; q += NTHREADS) {
            int xi = q & 3;
            int cq = (q >> 2) & 7;
            int rb = q >> 5;
            int r  = rb / 34;
            int xb = rb - r * 34;
            int pxi = xb * 4 + xi;        // 0..135
            int x   = pxi - 4;
            int yy  = y0 + r - 4;
            ull v0 = 0ull, v1 = 0ull;
            if (yy >= 0 && yy < HH && x >= 0 && x < WW) {
                ulonglong2 v = *reinterpret_cast<const ulonglong2*>(
                    F2 + (((size_t)(b * HH + yy) * WW + x) * CC_TOT + c0 + 4 * cq));
                v0 = v.x; v1 = v.y;       // (c, c+1), (c+2, c+3)
            }
            int e = spos(pxi);
            ull* dst = F2u + ((size_t)r * NCP + 2 * cq) * RLEN + e;
            dst[0]    = v0;               // cpair row 2cq
            dst[RLEN] = v1;               // cpair row 2cq+1
        }
        // ---- F1 fill: 2 rows, pxi 0..127 ----
        for (int q = tid; q < ROWS_PER_CTA * 128 * 8; q += NTHREADS) {
            int xi = q & 3;
            int cq = (q >> 2) & 7;
            int rb = q >> 5;
            int r2 = rb >> 5;
            int xb = rb & 31;
            int pxi = xb * 4 + xi;
            ulonglong2 v = *reinterpret_cast<const ulonglong2*>(
                F1 + (((size_t)(b * HH + y0 + r2) * WW + pxi) * CC_TOT + c0 + 4 * cq));
            int e = spos(pxi);
            ull* dst = F1u + ((size_t)r2 * NCP + 2 * cq) * RLEN + e;
            dst[0]    = v.x;
            dst[RLEN] = v.y;
        }
        __syncthreads();

        // ---- compute: 16 channel-pair rows ----
        const ulonglong2* f2b = reinterpret_cast<const ulonglong2*>(
            F2u + (size_t)(row + dy) * NCP * RLEN);
        const ulonglong2* f1b = reinterpret_cast<const ulonglong2*>(
            F1u + (size_t)row * NCP * RLEN);

#pragma unroll 2
        for (int cp = 0; cp < NCP; cp++) {
            const ulonglong2* f2r = f2b + (size_t)cp * (RLEN / 2);
            const ulonglong2* f1r = f1b + (size_t)cp * (RLEN / 2);

            ulonglong2 A0 = f1r[vj[0]];   // F1 px 4g..4g+1 (ch pair)
            ulonglong2 A1 = f1r[vj[1]];   // F1 px 4g+2..4g+3
            ull a[4] = { A0.x, A0.y, A1.x, A1.y };

            // first half: V f4 0..2 -> window f2 t = 0..5 (pxi 4g..4g+5)
            {
                ulonglong2 V0 = f2r[vj[0]];
                ulonglong2 V1 = f2r[vj[1]];
                ulonglong2 V2 = f2r[vj[2]];
                ull t0 = V0.x, t1 = V0.y, t2 = V1.x, t3 = V1.y, t4 = V2.x, t5 = V2.y;
                // acc[i][t-i] += a[i] * vt  for valid i (t-i = dx in 0..8)
                ffma2(acc[0][0], a[0], t0);
                ffma2(acc[0][1], a[0], t1); ffma2(acc[1][0], a[1], t1);
                ffma2(acc[0][2], a[0], t2); ffma2(acc[1][1], a[1], t2); ffma2(acc[2][0], a[2], t2);
                ffma2(acc[0][3], a[0], t3); ffma2(acc[1][2], a[1], t3); ffma2(acc[2][1], a[2], t3); ffma2(acc[3][0], a[3], t3);
                ffma2(acc[0][4], a[0], t4); ffma2(acc[1][3], a[1], t4); ffma2(acc[2][2], a[2], t4); ffma2(acc[3][1], a[3], t4);
                ffma2(acc[0][5], a[0], t5); ffma2(acc[1][4], a[1], t5); ffma2(acc[2][3], a[2], t5); ffma2(acc[3][2], a[3], t5);
            }
            // second half: V f4 3..5 -> window f2 t = 6..11 (pxi 4g+6..4g+11)
            {
                ulonglong2 V3 = f2r[vj[3]];
                ulonglong2 V4 = f2r[vj[4]];
                ulonglong2 V5 = f2r[vj[5]];
                ull t6 = V3.x, t7 = V3.y, t8 = V4.x, t9 = V4.y, t10 = V5.x, t11 = V5.y;
                ffma2(acc[0][6], a[0], t6); ffma2(acc[1][5], a[1], t6); ffma2(acc[2][4], a[2], t6); ffma2(acc[3][3], a[3], t6);
                ffma2(acc[0][7], a[0], t7); ffma2(acc[1][6], a[1], t7); ffma2(acc[2][5], a[2], t7); ffma2(acc[3][4], a[3], t7);
                ffma2(acc[0][8], a[0], t8); ffma2(acc[1][7], a[1], t8); ffma2(acc[2][6], a[2], t8); ffma2(acc[3][5], a[3], t8);
                ffma2(acc[1][8], a[1], t9); ffma2(acc[2][7], a[2], t9); ffma2(acc[3][6], a[3], t9);
                ffma2(acc[2][8], a[2], t10); ffma2(acc[3][7], a[3], t10);
                ffma2(acc[3][8], a[3], t11);
            }
        }
    }

    // ---- finalize: (lo+hi)*inv, leaky relu; stage both rows; coalesced copy ----
    __syncthreads();
    {
        float* ob = reinterpret_cast<float*>(smemu);   // 2*128*81 floats = 82944 B
        const float inv = 1.0f / 128.0f;
#pragma unroll
        for (int i = 0; i < 4; i++) {
            int px = 4 * g + i;
#pragma unroll
            for (int dx = 0; dx < 9; dx++) {
                ull a = acc[i][dx];
                float v = (__uint_as_float((unsigned int)a) +
                           __uint_as_float((unsigned int)(a >> 32))) * inv;
                v = v > 0.f ? v : 0.1f * v;
                ob[(size_t)row * WW * KDISP + px * KDISP + dy * 9 + dx] = v;
            }
        }
    }
    __syncthreads();
    {
        const float4* obv = reinterpret_cast<const float4*>(smemu);
        float4* ov = reinterpret_cast<float4*>(
            out + ((size_t)(b * HH + y0)) * WW * KDISP);
        for (int q = tid; q < (ROWS_PER_CTA * WW * KDISP) / 4; q += NTHREADS) {
            ov[q] = obv[q];
        }
    }
}

extern "C" void kernel_launch(void* const* d_in, const int* in_sizes, int n_in,
                              void* d_out, int out_size)
{
    const float* F1 = (const float*)d_in[0];
    const float* F2 = (const float*)d_in[1];
    float* out = (float*)d_out;

    cudaFuncSetAttribute(corr_kernel, cudaFuncAttributeMaxDynamicSharedMemorySize, SMEM_BYTES);

    dim3 grid(HH / ROWS_PER_CTA, BB);   // (y-pair, b)
    dim3 block(NTHREADS);
    corr_kernel<<<grid, block, SMEM_BYTES>>>(F1, F2, out);
}

// round 7
// speedup vs baseline: 1.4905x; 1.4905x over previous
#include <cuda_runtime.h>

// CostVolumeCorrelationLayer: B=8, H=W=128, C=128, maxDisp=4 -> 81 displacements
// out[b,y,x, dy*9+dx] = leaky_relu( mean_c( F1[b,y,x,c] * F2pad[b,y+dy,x+dx,c] ), 0.1 )
//
// Round-7: R3 structure + software-pipelined fill (register prefetch, double
// smem buffer). All 18 warps both fill and compute; LDG for chunk k+1 issues
// before compute of chunk k -> DRAM latency hidden behind FFMA2 phase.
//  - CCH=8 channels/chunk, 16 chunks, one __syncthreads per chunk.
//  - smem rows = single channels, 144 floats stride (== 16 mod 32) -> fill's
//    4-channel transpose scatter STS.32 is bank-conflict-free; compute LDS.128
//    reads f4 index g within one row -> contiguous, conflict-free.

#define BB 8
#define HH 128
#define WW 128
#define CC_TOT 128
#define KDISP 81

#define CCH 8
#define NCHUNK (CC_TOT / CCH)     // 16
#define NTHREADS 576              // 18 warps = (row 0..1, dy 0..8)
#define ROWS_PER_CTA 2
#define F2ROWS 10

#define ROWF 144                  // floats per channel row (needs 136; 144 % 32 == 16)
#define ROWF4 (ROWF / 4)          // 36
#define F2_FLOATS (F2ROWS * CCH * ROWF)        // 11520
#define F1_FLOATS (ROWS_PER_CTA * CCH * ROWF)  // 2304
#define BUF_FLOATS (F2_FLOATS + F1_FLOATS)     // 13824 (55296 B)
#define SMEM_BYTES (2 * BUF_FLOATS * 4)        // 110592 B

#define NF2ITEM (F2ROWS * 136 * 2)             // 2720 (px,cq) items per chunk
#define NF2 5                                  // ceil(2720/576)

using ull = unsigned long long;

__device__ __forceinline__ void ffma2(ull &acc, ull a, ull b) {
    asm("fma.rn.f32x2 %0, %1, %2, %0;" : "+l"(acc) : "l"(a), "l"(b));
}

__global__ __launch_bounds__(NTHREADS, 1)
void corr_kernel(const float* __restrict__ F1,
                 const float* __restrict__ F2,
                 float* __restrict__ out)
{
    extern __shared__ float smemf[];

    const int y0  = blockIdx.x * 2;
    const int b   = blockIdx.y;
    const int tid = threadIdx.x;
    const int w   = tid >> 5;
    const int g   = tid & 31;
    const int row = (w >= 9) ? 1 : 0;
    const int dy  = w - 9 * row;

    // ---- chunk-invariant fill indices ----
    // F2 item q: cq = q&1 (channel quad), t = q>>1 -> r = t/136, px = t%136
    long f2goff[NF2];     // gmem float offset (without c0); -1 => item absent
    int  f2soff[NF2];     // smem float offset (row base: + 2k*ROWF for k=0..3)
    bool f2zero[NF2];     // inside padding -> store zeros
#pragma unroll
    for (int i = 0; i < NF2; i++) {
        int q = tid + i * NTHREADS;
        if (q < NF2ITEM) {
            int cq = q & 1;
            int t  = q >> 1;
            int r  = t / 136;
            int px = t - r * 136;
            int x  = px - 4;
            int yy = y0 + r - 4;
            bool valid = (yy >= 0 && yy < HH && x >= 0 && x < WW);
            f2zero[i] = !valid;
            f2goff[i] = valid ? (((long)(b * HH + yy) * WW + x) * CC_TOT + 4 * cq) : 0;
            f2soff[i] = r * (CCH * ROWF) + cq * ROWF + px;
        } else {
            f2goff[i] = -1;
        }
    }
    long f1goff = -1; int f1soff = 0;
    if (tid < ROWS_PER_CTA * 128 * 2) {
        int cq = tid & 1;
        int t  = tid >> 1;
        int r2 = t >> 7;
        int px = t & 127;
        f1goff = ((long)(b * HH + y0 + r2) * WW + px) * CC_TOT + 4 * cq;
        f1soff = F2_FLOATS + r2 * (CCH * ROWF) + cq * ROWF + px;
    }

    ull acc[2][9];
#pragma unroll
    for (int i = 0; i < 2; i++)
#pragma unroll
        for (int dx = 0; dx < 9; dx++) acc[i][dx] = 0ull;

    // ---- prefetch chunk 0 ----
    float4 pf[NF2], pf1;
#pragma unroll
    for (int i = 0; i < NF2; i++) {
        pf[i] = make_float4(0.f, 0.f, 0.f, 0.f);
        if (f2goff[i] >= 0 && !f2zero[i])
            pf[i] = __ldcg(reinterpret_cast<const float4*>(F2 + f2goff[i]));
    }
    pf1 = make_float4(0.f, 0.f, 0.f, 0.f);
    if (f1goff >= 0)
        pf1 = __ldcg(reinterpret_cast<const float4*>(F1 + f1goff));

    for (int ck = 0; ck < NCHUNK; ck++) {
        float* buf = smemf + (size_t)(ck & 1) * BUF_FLOATS;

        // ---- STS: drain prefetch regs into smem (channels c0.. -> rows 2k+cq) ----
#pragma unroll
        for (int i = 0; i < NF2; i++) {
            if (f2goff[i] >= 0) {
                float* d = buf + f2soff[i];
                d[0 * ROWF] = pf[i].x;
                d[2 * ROWF] = pf[i].y;
                d[4 * ROWF] = pf[i].z;
                d[6 * ROWF] = pf[i].w;
            }
        }
        if (f1goff >= 0) {
            float* d = buf + f1soff;
            d[0 * ROWF] = pf1.x;
            d[2 * ROWF] = pf1.y;
            d[4 * ROWF] = pf1.z;
            d[6 * ROWF] = pf1.w;
        }
        __syncthreads();   // buffer full for all; prev compute on this buffer done (2 iters ago)

        // ---- issue LDG prefetch for chunk ck+1 (consumed next iteration) ----
        if (ck + 1 < NCHUNK) {
            const int c0 = (ck + 1) * CCH;
#pragma unroll
            for (int i = 0; i < NF2; i++) {
                if (f2goff[i] >= 0 && !f2zero[i])
                    pf[i] = __ldcg(reinterpret_cast<const float4*>(F2 + f2goff[i] + c0));
            }
            if (f1goff >= 0)
                pf1 = __ldcg(reinterpret_cast<const float4*>(F1 + f1goff + c0));
        }

        // ---- compute chunk ck: 8 channel rows ----
        const float4* f2b = reinterpret_cast<const float4*>(buf) + (size_t)(row + dy) * CCH * ROWF4;
        const float4* f1b = reinterpret_cast<const float4*>(buf + F2_FLOATS) + (size_t)row * CCH * ROWF4;

#pragma unroll
        for (int cr = 0; cr < CCH; cr++) {
            const ulonglong2* f1r = reinterpret_cast<const ulonglong2*>(f1b + (size_t)cr * ROWF4);
            const ulonglong2* f2r = reinterpret_cast<const ulonglong2*>(f2b + (size_t)cr * ROWF4);

            ulonglong2 A  = f1r[g];        // F1 px 4g..4g+3
            ulonglong2 V0 = f2r[g];        // F2 px 4g-4..4g-1
            ulonglong2 V1 = f2r[g + 1];    // F2 px 4g..4g+3
            ulonglong2 V2 = f2r[g + 2];    // F2 px 4g+4..4g+7

            ull f1a = A.x, f1bb = A.y;
            ull vp[6] = { V0.x, V0.y, V1.x, V1.y, V2.x, V2.y };

            ull m[5];
#pragma unroll
            for (int j = 0; j < 5; j++) {
                unsigned int lo = (unsigned int)(vp[j] >> 32);
                unsigned int hi = (unsigned int)(vp[j + 1]);
                asm("mov.b64 %0, {%1,%2};" : "=l"(m[j]) : "r"(lo), "r"(hi));
            }
#pragma unroll
            for (int e = 0; e < 5; e++) {
                ffma2(acc[0][2 * e], f1a,  vp[e]);
                ffma2(acc[1][2 * e], f1bb, vp[e + 1]);
            }
#pragma unroll
            for (int o = 0; o < 4; o++) {
                ffma2(acc[0][2 * o + 1], f1a,  m[o]);
                ffma2(acc[1][2 * o + 1], f1bb, m[o + 1]);
            }
        }
    }

    // ---- finalize: mean + leaky relu; stage both rows; coalesced copy ----
    __syncthreads();
    {
        float* ob = smemf;   // 2*128*81 floats = 82944 B (fits in 110592)
        const float inv = 1.0f / 128.0f;
#pragma unroll
        for (int i = 0; i < 2; i++) {
            int px = 4 * g + 2 * i;
#pragma unroll
            for (int dx = 0; dx < 9; dx++) {
                ull a = acc[i][dx];
                float v0 = __uint_as_float((unsigned int)a) * inv;
                float v1 = __uint_as_float((unsigned int)(a >> 32)) * inv;
                v0 = v0 > 0.f ? v0 : 0.1f * v0;
                v1 = v1 > 0.f ? v1 : 0.1f * v1;
                int k = dy * 9 + dx;
                ob[(size_t)row * WW * KDISP + px * KDISP + k]       = v0;
                ob[(size_t)row * WW * KDISP + (px + 1) * KDISP + k] = v1;
            }
        }
    }
    __syncthreads();
    {
        const float4* obv = reinterpret_cast<const float4*>(smemf);
        float4* ov = reinterpret_cast<float4*>(
            out + ((size_t)(b * HH + y0)) * WW * KDISP);
        for (int q = tid; q < (ROWS_PER_CTA * WW * KDISP) / 4; q += NTHREADS) {
            ov[q] = obv[q];
        }
    }
}

extern "C" void kernel_launch(void* const* d_in, const int* in_sizes, int n_in,
                              void* d_out, int out_size)
{
    const float* F1 = (const float*)d_in[0];
    const float* F2 = (const float*)d_in[1];
    float* out = (float*)d_out;

    cudaFuncSetAttribute(corr_kernel, cudaFuncAttributeMaxDynamicSharedMemorySize, SMEM_BYTES);

    dim3 grid(HH / ROWS_PER_CTA, BB);   // (y-pair, b)
    dim3 block(NTHREADS);
    corr_kernel<<<grid, block, SMEM_BYTES>>>(F1, F2, out);
}

// round 9
// speedup vs baseline: 1.8268x; 1.2257x over previous
#include <cuda_runtime.h>
#include <cuda_bf16.h>
#include <cstdint>

// CostVolumeCorrelationLayer via banded bf16-split GEMM on legacy tensor cores
// (mma.sync m16n8k16 — compiles for plain sm_100 target; tcgen05 does not).
// Per (b,y,dy): D[x][j] = sum_c F1[x,c] * B[j,c], B[j,:] = F2pad[y+dy-4, j-4, :].
// Wanted band: dx = j - x in 0..8. m-tile 16 rows -> j in [16m, 16m+24) = 3 n-tiles.
// fp32 = bf16 hi + lo; D = hi*hi + hi*lo + lo*hi (lo*lo dropped, ~2^-17 rel).

#define BB 8
#define HH 128
#define WW 128
#define CC 128
#define KD 81
#define NTHREADS 256

#define KH 136                    // halves per smem row (128 + 8 pad)
#define ROWB (KH * 2)             // 272 bytes; 272*r mod 128 cycles 8 slots -> ldmatrix conflict-free
#define A_HI  0
#define A_LO  (128 * ROWB)                  // 34816
#define B_HI  (2 * 128 * ROWB)              // 69632
#define B_LO  (B_HI + 136 * ROWB)           // 106624
#define STAGE (B_LO + 136 * ROWB)           // 143616 (raw fp32 F2 row, 64KB)
#define SMEM_BYTES (STAGE + 128 * 512)      // 209152

__device__ __forceinline__ uint32_t smem_u32(const void* p) {
    uint32_t a;
    asm("{ .reg .u64 t; cvta.to.shared.u64 t, %1; cvt.u32.u64 %0, t; }" : "=r"(a) : "l"(p));
    return a;
}
__device__ __forceinline__ void ldsm_x4(uint32_t* r, uint32_t addr) {
    asm volatile("ldmatrix.sync.aligned.m8n8.x4.shared.b16 {%0,%1,%2,%3}, [%4];"
                 : "=r"(r[0]), "=r"(r[1]), "=r"(r[2]), "=r"(r[3]) : "r"(addr));
}
__device__ __forceinline__ void ldsm_x2(uint32_t* r, uint32_t addr) {
    asm volatile("ldmatrix.sync.aligned.m8n8.x2.shared.b16 {%0,%1}, [%2];"
                 : "=r"(r[0]), "=r"(r[1]) : "r"(addr));
}
__device__ __forceinline__ void mma16816(float* d, const uint32_t* a, const uint32_t* b) {
    asm volatile("mma.sync.aligned.m16n8k16.row.col.f32.bf16.bf16.f32 "
                 "{%0,%1,%2,%3}, {%4,%5,%6,%7}, {%8,%9}, {%0,%1,%2,%3};"
                 : "+f"(d[0]), "+f"(d[1]), "+f"(d[2]), "+f"(d[3])
                 : "r"(a[0]), "r"(a[1]), "r"(a[2]), "r"(a[3]), "r"(b[0]), "r"(b[1]));
}
__device__ __forceinline__ void cp16(uint32_t dst, const void* src) {
    asm volatile("cp.async.cg.shared.global [%0], [%1], 16;" :: "r"(dst), "l"(src));
}

// hi = truncate-to-bf16 (exact residual), lo = rn(v - hi). Store 4 channels.
__device__ __forceinline__ void split_store(float4 v, char* hip, char* lop) {
    uint32_t u0 = __float_as_uint(v.x), u1 = __float_as_uint(v.y);
    uint32_t u2 = __float_as_uint(v.z), u3 = __float_as_uint(v.w);
    uint32_t h0 = __byte_perm(u0, u1, 0x7632);
    uint32_t h1 = __byte_perm(u2, u3, 0x7632);
    float l0 = v.x - __uint_as_float(u0 & 0xFFFF0000u);
    float l1 = v.y - __uint_as_float(u1 & 0xFFFF0000u);
    float l2 = v.z - __uint_as_float(u2 & 0xFFFF0000u);
    float l3 = v.w - __uint_as_float(u3 & 0xFFFF0000u);
    uint32_t p0, p1;
    asm("cvt.rn.bf16x2.f32 %0, %1, %2;" : "=r"(p0) : "f"(l1), "f"(l0));
    asm("cvt.rn.bf16x2.f32 %0, %1, %2;" : "=r"(p1) : "f"(l3), "f"(l2));
    *reinterpret_cast<uint2*>(hip) = make_uint2(h0, h1);
    *reinterpret_cast<uint2*>(lop) = make_uint2(p0, p1);
}

__global__ __launch_bounds__(NTHREADS, 1)
void corr_mma_kernel(const float* __restrict__ F1,
                     const float* __restrict__ F2,
                     float* __restrict__ out)
{
    extern __shared__ char smem[];
    const uint32_t sb  = smem_u32(smem);
    const int tid  = threadIdx.x;
    const int w    = tid >> 5;          // m-tile 0..7
    const int lane = tid & 31;
    const int y = blockIdx.x, b = blockIdx.y;

    // ---- stage F2 row for dy=0 via cp.async (64KB linear copy) ----
    {
        int yy = y - 4;
        if (yy >= 0 && yy < HH) {
            const float* f2p = F2 + ((size_t)(b * HH + yy)) * WW * CC;
            for (int it = tid; it < 128 * 32; it += NTHREADS)
                cp16(sb + STAGE + it * 16, f2p + 4 * it);
        }
        asm volatile("cp.async.commit_group;" ::: "memory");
    }

    // ---- convert A = F1 row to bf16 hi/lo smem tiles ----
    const float* f1p = F1 + ((size_t)(b * HH + y)) * WW * CC;
#pragma unroll 4
    for (int it = tid; it < 128 * 32; it += NTHREADS) {
        int x = it >> 5, q = it & 31;
        float4 v = __ldcg(reinterpret_cast<const float4*>(f1p + (size_t)x * CC + 4 * q));
        split_store(v, smem + A_HI + x * ROWB + 8 * q, smem + A_LO + x * ROWB + 8 * q);
    }
    __syncthreads();

    // ---- load A fragments (all k-steps, hi+lo) into registers ----
    uint32_t ahi[8][4], alo[8][4];
    {
        const int x0 = 16 * w;
        uint32_t arow = sb + A_HI + (uint32_t)(x0 + (lane & 15)) * ROWB + ((lane >> 4) << 4);
#pragma unroll
        for (int s = 0; s < 8; s++) ldsm_x4(ahi[s], arow + 32 * s);
        arow += (A_LO - A_HI);
#pragma unroll
        for (int s = 0; s < 8; s++) ldsm_x4(alo[s], arow + 32 * s);
    }

    // B fragment base addresses (per n-tile)
    uint32_t bhib[3], blob[3];
#pragma unroll
    for (int nt = 0; nt < 3; nt++) {
        uint32_t r = (uint32_t)(16 * w + 8 * nt + (lane & 7)) * ROWB + ((lane & 8) ? 16 : 0);
        bhib[nt] = sb + B_HI + r;
        blob[nt] = sb + B_LO + r;
    }

    const float inv = 1.0f / 128.0f;
    const int x0 = 16 * w;

    for (int dy = 0; dy < 9; dy++) {
        // ---- wait staged raw row; convert to bf16 hi/lo B tiles ----
        asm volatile("cp.async.wait_group 0;" ::: "memory");
        __syncthreads();   // staging ready for all; prev mma reads of B done
        {
            int yy = y + dy - 4;
            bool vr = (yy >= 0 && yy < HH);
            const float* stg = reinterpret_cast<const float*>(smem + STAGE);
#pragma unroll 4
            for (int it = tid; it < 136 * 32; it += NTHREADS) {
                int j = it >> 5, q = it & 31;
                int x2 = j - 4;
                float4 v = make_float4(0.f, 0.f, 0.f, 0.f);
                if (vr && x2 >= 0 && x2 < WW)
                    v = *reinterpret_cast<const float4*>(stg + (size_t)x2 * 128 + 4 * q);
                split_store(v, smem + B_HI + j * ROWB + 8 * q, smem + B_LO + j * ROWB + 8 * q);
            }
        }
        __syncthreads();

        // ---- prefetch next dy's raw F2 row (overlaps mma below) ----
        if (dy < 8) {
            int yn = y + dy + 1 - 4;
            if (yn >= 0 && yn < HH) {
                const float* f2p = F2 + ((size_t)(b * HH + yn)) * WW * CC;
                for (int it = tid; it < 128 * 32; it += NTHREADS)
                    cp16(sb + STAGE + it * 16, f2p + 4 * it);
            }
            asm volatile("cp.async.commit_group;" ::: "memory");
        }

        // ---- banded GEMM: 3 n-tiles x 8 k-steps x 3 passes ----
        float acc[3][4];
#pragma unroll
        for (int nt = 0; nt < 3; nt++)
#pragma unroll
            for (int e = 0; e < 4; e++) acc[nt][e] = 0.f;

#pragma unroll
        for (int s = 0; s < 8; s++) {
#pragma unroll
            for (int nt = 0; nt < 3; nt++) {
                uint32_t bh[2], bl[2];
                ldsm_x2(bh, bhib[nt] + 32 * s);
                mma16816(acc[nt], ahi[s], bh);   // hi*hi
                mma16816(acc[nt], alo[s], bh);   // lo*hi
                ldsm_x2(bl, blob[nt] + 32 * s);
                mma16816(acc[nt], ahi[s], bl);   // hi*lo
            }
        }

        // ---- banded epilogue: dx = j - x in [0,8] -> scattered STG ----
        const int rb = lane >> 2, cb = 2 * (lane & 3);
#pragma unroll
        for (int nt = 0; nt < 3; nt++) {
            const int n0 = 16 * w + 8 * nt;
#pragma unroll
            for (int h = 0; h < 2; h++) {
                const int x = x0 + rb + 8 * h;
                float* op = out + (((size_t)(b * HH + y)) * WW + x) * KD + 9 * dy;
#pragma unroll
                for (int e = 0; e < 2; e++) {
                    const int dx = n0 + cb + e - x;
                    if (dx >= 0 && dx <= 8) {
                        float v = acc[nt][2 * h + e] * inv;
                        v = v > 0.f ? v : 0.1f * v;
                        op[dx] = v;
                    }
                }
            }
        }
    }
}

extern "C" void kernel_launch(void* const* d_in, const int* in_sizes, int n_in,
                              void* d_out, int out_size)
{
    const float* F1 = (const float*)d_in[0];
    const float* F2 = (const float*)d_in[1];
    float* out = (float*)d_out;

    cudaFuncSetAttribute(corr_mma_kernel, cudaFuncAttributeMaxDynamicSharedMemorySize, SMEM_BYTES);

    dim3 grid(HH, BB);     // (y, b): y-adjacent CTAs reuse F2 rows in L2
    dim3 block(NTHREADS);
    corr_mma_kernel<<<grid, block, SMEM_BYTES>>>(F1, F2, out);
}

// round 10
// speedup vs baseline: 2.1133x; 1.1568x over previous
#include <cuda_runtime.h>
#include <cuda_bf16.h>
#include <cstdint>

// CostVolumeCorrelationLayer via banded bf16-split GEMM on mma.sync (m16n8k16).
// Per (b,y,dy): D[x][j] = sum_c F1[x,c] * B[j,c], B[j,:] = F2pad[y+dy-4, j-4, :].
// Band dx = j - x in 0..8; m-tile 16 rows -> 3 aligned n-tiles of 8.
// fp32 = bf16 hi + lo; D = hi*hi + hi*lo + lo*hi.
//
// Round-10: smem diet for 2 CTAs/SM. No cp.async stage (direct LDG convert);
// A smem region reused as the B buffer after A fragments move to registers.
// Cross-CTA overlap hides both conversion latency and phase serialization.

#define BB 8
#define HH 128
#define WW 128
#define CC 128
#define KD 81
#define NTHREADS 256

#define ROWB 272                 // bytes per 128-ch bf16 row (+8 halves pad); 272%128=16 -> ldmatrix conflict-free
#define A_HI  0
#define A_LO  (128 * ROWB)       // 34816   (A region: init only)
#define B_HI  0
#define B_LO  (136 * ROWB)       // 36992   (B region overlays A after init)
#define SMEM_BYTES (2 * 136 * ROWB)   // 73984 -> 2 CTAs/SM

__device__ __forceinline__ uint32_t smem_u32(const void* p) {
    uint32_t a;
    asm("{ .reg .u64 t; cvta.to.shared.u64 t, %1; cvt.u32.u64 %0, t; }" : "=r"(a) : "l"(p));
    return a;
}
__device__ __forceinline__ void ldsm_x4(uint32_t* r, uint32_t addr) {
    asm volatile("ldmatrix.sync.aligned.m8n8.x4.shared.b16 {%0,%1,%2,%3}, [%4];"
                 : "=r"(r[0]), "=r"(r[1]), "=r"(r[2]), "=r"(r[3]) : "r"(addr));
}
__device__ __forceinline__ void ldsm_x2(uint32_t* r, uint32_t addr) {
    asm volatile("ldmatrix.sync.aligned.m8n8.x2.shared.b16 {%0,%1}, [%2];"
                 : "=r"(r[0]), "=r"(r[1]) : "r"(addr));
}
__device__ __forceinline__ void mma16816(float* d, const uint32_t* a, const uint32_t* b) {
    asm volatile("mma.sync.aligned.m16n8k16.row.col.f32.bf16.bf16.f32 "
                 "{%0,%1,%2,%3}, {%4,%5,%6,%7}, {%8,%9}, {%0,%1,%2,%3};"
                 : "+f"(d[0]), "+f"(d[1]), "+f"(d[2]), "+f"(d[3])
                 : "r"(a[0]), "r"(a[1]), "r"(a[2]), "r"(a[3]), "r"(b[0]), "r"(b[1]));
}

// hi = truncate-to-bf16 (exact residual), lo = rn(v - hi). Store 4 channels (8B hi + 8B lo).
__device__ __forceinline__ void split_store(float4 v, char* hip, char* lop) {
    uint32_t u0 = __float_as_uint(v.x), u1 = __float_as_uint(v.y);
    uint32_t u2 = __float_as_uint(v.z), u3 = __float_as_uint(v.w);
    uint32_t h0 = __byte_perm(u0, u1, 0x7632);
    uint32_t h1 = __byte_perm(u2, u3, 0x7632);
    float l0 = v.x - __uint_as_float(u0 & 0xFFFF0000u);
    float l1 = v.y - __uint_as_float(u1 & 0xFFFF0000u);
    float l2 = v.z - __uint_as_float(u2 & 0xFFFF0000u);
    float l3 = v.w - __uint_as_float(u3 & 0xFFFF0000u);
    uint32_t p0, p1;
    asm("cvt.rn.bf16x2.f32 %0, %1, %2;" : "=r"(p0) : "f"(l1), "f"(l0));
    asm("cvt.rn.bf16x2.f32 %0, %1, %2;" : "=r"(p1) : "f"(l3), "f"(l2));
    *reinterpret_cast<uint2*>(hip) = make_uint2(h0, h1);
    *reinterpret_cast<uint2*>(lop) = make_uint2(p0, p1);
}

__global__ __launch_bounds__(NTHREADS, 2)
void corr_mma_kernel(const float* __restrict__ F1,
                     const float* __restrict__ F2,
                     float* __restrict__ out)
{
    extern __shared__ char smem[];
    const uint32_t sb  = smem_u32(smem);
    const int tid  = threadIdx.x;
    const int w    = tid >> 5;          // m-tile 0..7
    const int lane = tid & 31;
    const int y = blockIdx.x, b = blockIdx.y;

    // ---- convert A = F1 row to bf16 hi/lo smem tiles (init-only region) ----
    const float* f1p = F1 + ((size_t)(b * HH + y)) * WW * CC;
#pragma unroll 4
    for (int it = tid; it < 128 * 32; it += NTHREADS) {
        int x = it >> 5, q = it & 31;
        float4 v = __ldcg(reinterpret_cast<const float4*>(f1p + (size_t)x * CC + 4 * q));
        split_store(v, smem + A_HI + x * ROWB + 8 * q, smem + A_LO + x * ROWB + 8 * q);
    }
    __syncthreads();

    // ---- A fragments (all 8 k-steps, hi+lo) -> registers ----
    uint32_t ahi[8][4], alo[8][4];
    {
        uint32_t arow = sb + A_HI + (uint32_t)(16 * w + (lane & 15)) * ROWB + ((lane >> 4) << 4);
#pragma unroll
        for (int s = 0; s < 8; s++) ldsm_x4(ahi[s], arow + 32 * s);
        arow += (uint32_t)(A_LO - A_HI);
#pragma unroll
        for (int s = 0; s < 8; s++) ldsm_x4(alo[s], arow + 32 * s);
    }
    __syncthreads();   // A smem reads complete -> region becomes the B buffer

    // ---- B fragment base addresses per n-tile ----
    uint32_t bhib[3], blob[3];
#pragma unroll
    for (int nt = 0; nt < 3; nt++) {
        uint32_t r = (uint32_t)(16 * w + 8 * nt + (lane & 7)) * ROWB + ((lane & 8) ? 16 : 0);
        bhib[nt] = sb + B_HI + r;
        blob[nt] = sb + B_LO + r;
    }

    const float inv = 1.0f / 128.0f;
    const int x0 = 16 * w;

    for (int dy = 0; dy < 9; dy++) {
        // ---- convert B row (direct from gmem; 17 indep LDG.128/thread -> high MLP) ----
        {
            int yy = y + dy - 4;
            bool vr = (yy >= 0 && yy < HH);
            const float* f2p = F2 + ((size_t)(b * HH + (vr ? yy : 0))) * WW * CC;
#pragma unroll 4
            for (int it = tid; it < 136 * 32; it += NTHREADS) {
                int j = it >> 5, q = it & 31;
                int x2 = j - 4;
                float4 v = make_float4(0.f, 0.f, 0.f, 0.f);
                if (vr && x2 >= 0 && x2 < WW)
                    v = __ldcg(reinterpret_cast<const float4*>(f2p + (size_t)x2 * CC + 4 * q));
                split_store(v, smem + B_HI + j * ROWB + 8 * q, smem + B_LO + j * ROWB + 8 * q);
            }
        }
        __syncthreads();

        // ---- banded GEMM: 3 n-tiles x 8 k-steps x 3 bf16-split passes ----
        float acc[3][4];
#pragma unroll
        for (int nt = 0; nt < 3; nt++)
#pragma unroll
            for (int e = 0; e < 4; e++) acc[nt][e] = 0.f;

#pragma unroll
        for (int s = 0; s < 8; s++) {
#pragma unroll
            for (int nt = 0; nt < 3; nt++) {
                uint32_t bh[2], bl[2];
                ldsm_x2(bh, bhib[nt] + 32 * s);
                mma16816(acc[nt], ahi[s], bh);   // hi*hi
                mma16816(acc[nt], alo[s], bh);   // lo*hi
                ldsm_x2(bl, blob[nt] + 32 * s);
                mma16816(acc[nt], ahi[s], bl);   // hi*lo
            }
        }

        // ---- banded epilogue: dx = j - x in [0,8] -> masked STG ----
        const int rb = lane >> 2, cb = 2 * (lane & 3);
#pragma unroll
        for (int nt = 0; nt < 3; nt++) {
            const int n0 = 16 * w + 8 * nt;
#pragma unroll
            for (int h = 0; h < 2; h++) {
                const int x = x0 + rb + 8 * h;
                float* op = out + (((size_t)(b * HH + y)) * WW + x) * KD + 9 * dy;
#pragma unroll
                for (int e = 0; e < 2; e++) {
                    const int dx = n0 + cb + e - x;
                    if (dx >= 0 && dx <= 8) {
                        float v = acc[nt][2 * h + e] * inv;
                        v = v > 0.f ? v : 0.1f * v;
                        op[dx] = v;
                    }
                }
            }
        }
        __syncthreads();   // all ldsm reads of B done before next conversion
    }
}

extern "C" void kernel_launch(void* const* d_in, const int* in_sizes, int n_in,
                              void* d_out, int out_size)
{
    const float* F1 = (const float*)d_in[0];
    const float* F2 = (const float*)d_in[1];
    float* out = (float*)d_out;

    cudaFuncSetAttribute(corr_mma_kernel, cudaFuncAttributeMaxDynamicSharedMemorySize, SMEM_BYTES);

    dim3 grid(HH, BB);     // (y, b): y-adjacent CTAs reuse F2 rows in L2
    dim3 block(NTHREADS);
    corr_mma_kernel<<<grid, block, SMEM_BYTES>>>(F1, F2, out);
}

// round 11
// speedup vs baseline: 2.1735x; 1.0285x over previous
#include <cuda_runtime.h>
#include <cuda_bf16.h>
#include <cstdint>

// CostVolumeCorrelationLayer via banded bf16-split GEMM on mma.sync (m16n8k16).
// Round-11: two-pass. Kernel 1 splits F2 fp32 -> bf16 hi/lo scratch ONCE
// (previously every F2 row was re-split by 9 CTAs). Kernel 2 = R10 with the
// B-conversion replaced by cp.async copies from scratch (no ALU in hot loop).

#define BB 8
#define HH 128
#define WW 128
#define CC 128
#define KD 81
#define NTHREADS 256

#define ROWB 272                 // bytes/row of bf16 tile (+16B pad); 272%128=16 -> ldmatrix conflict-free
#define A_HI  0
#define A_LO  (128 * ROWB)       // A region: init only, overlaid by B afterwards
#define B_HI  0
#define B_LO  (136 * ROWB)       // 36992
#define SMEM_BYTES (2 * 136 * ROWB)   // 73984 -> 2 CTAs/SM

#define NELEM ((size_t)BB * HH * WW * CC)

__device__ __align__(16) __nv_bfloat16 g_hi[NELEM];   // 32 MB scratch
__device__ __align__(16) __nv_bfloat16 g_lo[NELEM];   // 32 MB scratch

__device__ __forceinline__ uint32_t smem_u32(const void* p) {
    uint32_t a;
    asm("{ .reg .u64 t; cvta.to.shared.u64 t, %1; cvt.u32.u64 %0, t; }" : "=r"(a) : "l"(p));
    return a;
}
__device__ __forceinline__ void ldsm_x4(uint32_t* r, uint32_t addr) {
    asm volatile("ldmatrix.sync.aligned.m8n8.x4.shared.b16 {%0,%1,%2,%3}, [%4];"
                 : "=r"(r[0]), "=r"(r[1]), "=r"(r[2]), "=r"(r[3]) : "r"(addr));
}
__device__ __forceinline__ void ldsm_x2(uint32_t* r, uint32_t addr) {
    asm volatile("ldmatrix.sync.aligned.m8n8.x2.shared.b16 {%0,%1}, [%2];"
                 : "=r"(r[0]), "=r"(r[1]) : "r"(addr));
}
__device__ __forceinline__ void mma16816(float* d, const uint32_t* a, const uint32_t* b) {
    asm volatile("mma.sync.aligned.m16n8k16.row.col.f32.bf16.bf16.f32 "
                 "{%0,%1,%2,%3}, {%4,%5,%6,%7}, {%8,%9}, {%0,%1,%2,%3};"
                 : "+f"(d[0]), "+f"(d[1]), "+f"(d[2]), "+f"(d[3])
                 : "r"(a[0]), "r"(a[1]), "r"(a[2]), "r"(a[3]), "r"(b[0]), "r"(b[1]));
}
__device__ __forceinline__ void cp16(uint32_t dst, const void* src) {
    asm volatile("cp.async.cg.shared.global [%0], [%1], 16;" :: "r"(dst), "l"(src));
}

// hi = truncate-to-bf16 (exact residual), lo = rn(v - hi). 4 channels.
__device__ __forceinline__ void split4(float4 v, uint2& hi, uint2& lo) {
    uint32_t u0 = __float_as_uint(v.x), u1 = __float_as_uint(v.y);
    uint32_t u2 = __float_as_uint(v.z), u3 = __float_as_uint(v.w);
    hi.x = __byte_perm(u0, u1, 0x7632);
    hi.y = __byte_perm(u2, u3, 0x7632);
    float l0 = v.x - __uint_as_float(u0 & 0xFFFF0000u);
    float l1 = v.y - __uint_as_float(u1 & 0xFFFF0000u);
    float l2 = v.z - __uint_as_float(u2 & 0xFFFF0000u);
    float l3 = v.w - __uint_as_float(u3 & 0xFFFF0000u);
    asm("cvt.rn.bf16x2.f32 %0, %1, %2;" : "=r"(lo.x) : "f"(l1), "f"(l0));
    asm("cvt.rn.bf16x2.f32 %0, %1, %2;" : "=r"(lo.y) : "f"(l3), "f"(l2));
}

// ---------------- Kernel 1: F2 fp32 -> bf16 hi/lo scratch (one pass) ----------------
__global__ __launch_bounds__(NTHREADS)
void split_kernel(const float* __restrict__ F2)
{
    const int row = blockIdx.x;                 // b*HH + y, 0..1023
    const float* src = F2 + (size_t)row * WW * CC;
    __nv_bfloat16* hp = g_hi + (size_t)row * WW * CC;
    __nv_bfloat16* lp = g_lo + (size_t)row * WW * CC;
#pragma unroll 4
    for (int it = threadIdx.x; it < 128 * 32; it += NTHREADS) {
        int x = it >> 5, q = it & 31;
        float4 v = __ldcg(reinterpret_cast<const float4*>(src + (size_t)x * CC + 4 * q));
        uint2 hi, lo;
        split4(v, hi, lo);
        *reinterpret_cast<uint2*>(hp + (size_t)x * CC + 4 * q) = hi;
        *reinterpret_cast<uint2*>(lp + (size_t)x * CC + 4 * q) = lo;
    }
}

// ---------------- Kernel 2: banded GEMM consuming scratch ----------------
__global__ __launch_bounds__(NTHREADS, 2)
void corr_mma_kernel(const float* __restrict__ F1,
                     float* __restrict__ out)
{
    extern __shared__ char smem[];
    const uint32_t sb  = smem_u32(smem);
    const int tid  = threadIdx.x;
    const int w    = tid >> 5;          // m-tile 0..7
    const int lane = tid & 31;
    const int y = blockIdx.x, b = blockIdx.y;

    // ---- convert A = F1 row to bf16 hi/lo smem tiles (init-only region) ----
    const float* f1p = F1 + ((size_t)(b * HH + y)) * WW * CC;
#pragma unroll 4
    for (int it = tid; it < 128 * 32; it += NTHREADS) {
        int x = it >> 5, q = it & 31;
        float4 v = __ldcg(reinterpret_cast<const float4*>(f1p + (size_t)x * CC + 4 * q));
        uint2 hi, lo;
        split4(v, hi, lo);
        *reinterpret_cast<uint2*>(smem + A_HI + x * ROWB + 8 * q) = hi;
        *reinterpret_cast<uint2*>(smem + A_LO + x * ROWB + 8 * q) = lo;
    }
    __syncthreads();

    // ---- A fragments (8 k-steps, hi+lo) -> registers ----
    uint32_t ahi[8][4], alo[8][4];
    {
        uint32_t arow = sb + A_HI + (uint32_t)(16 * w + (lane & 15)) * ROWB + ((lane >> 4) << 4);
#pragma unroll
        for (int s = 0; s < 8; s++) ldsm_x4(ahi[s], arow + 32 * s);
        arow += (uint32_t)(A_LO - A_HI);
#pragma unroll
        for (int s = 0; s < 8; s++) ldsm_x4(alo[s], arow + 32 * s);
    }
    __syncthreads();   // A smem reads complete -> region becomes the B buffer

    // ---- zero border columns j in {0..3, 132..135} once (never overwritten) ----
    for (int k = tid; k < 8 * 17; k += NTHREADS) {
        int jb = k / 17, c = k - 17 * jb;
        int j  = (jb < 4) ? jb : (jb + 128);
        uint32_t d = sb + (uint32_t)j * ROWB + 16 * c;
        *reinterpret_cast<uint4*>(smem + (d - sb) + B_HI) = make_uint4(0, 0, 0, 0);
        *reinterpret_cast<uint4*>(smem + (d - sb) + B_LO) = make_uint4(0, 0, 0, 0);
    }

    // ---- B fragment base addresses per n-tile ----
    uint32_t bhib[3], blob[3];
#pragma unroll
    for (int nt = 0; nt < 3; nt++) {
        uint32_t r = (uint32_t)(16 * w + 8 * nt + (lane & 7)) * ROWB + ((lane & 8) ? 16 : 0);
        bhib[nt] = sb + B_HI + r;
        blob[nt] = sb + B_LO + r;
    }

    const float inv = 1.0f / 128.0f;
    const int x0 = 16 * w;

    for (int dy = 0; dy < 9; dy++) {
        // ---- fill B interior (j=4..131) from scratch via cp.async ----
        const int yy = y + dy - 4;
        if (yy >= 0 && yy < HH) {
            const size_t rb = (size_t)(b * HH + yy) * WW * CC;
#pragma unroll
            for (int k = tid; k < 2048; k += NTHREADS) {   // 8 iters: 128 x * 16 chunks
                int x = k >> 4, qq = k & 15;
                uint32_t d = (uint32_t)(x + 4) * ROWB + 16 * qq;
                size_t so = rb + (size_t)x * CC + 8 * qq;
                cp16(sb + B_HI + d, g_hi + so);
                cp16(sb + B_LO + d, g_lo + so);
            }
            asm volatile("cp.async.commit_group;" ::: "memory");
            asm volatile("cp.async.wait_group 0;" ::: "memory");
        } else {
#pragma unroll
            for (int k = tid; k < 2048; k += NTHREADS) {
                int x = k >> 4, qq = k & 15;
                uint32_t d = (uint32_t)(x + 4) * ROWB + 16 * qq;
                *reinterpret_cast<uint4*>(smem + B_HI + d) = make_uint4(0, 0, 0, 0);
                *reinterpret_cast<uint4*>(smem + B_LO + d) = make_uint4(0, 0, 0, 0);
            }
        }
        __syncthreads();

        // ---- banded GEMM: 3 n-tiles x 8 k-steps x 3 bf16-split passes ----
        float acc[3][4];
#pragma unroll
        for (int nt = 0; nt < 3; nt++)
#pragma unroll
            for (int e = 0; e < 4; e++) acc[nt][e] = 0.f;

#pragma unroll
        for (int s = 0; s < 8; s++) {
#pragma unroll
            for (int nt = 0; nt < 3; nt++) {
                uint32_t bh[2], bl[2];
                ldsm_x2(bh, bhib[nt] + 32 * s);
                mma16816(acc[nt], ahi[s], bh);   // hi*hi
                mma16816(acc[nt], alo[s], bh);   // lo*hi
                ldsm_x2(bl, blob[nt] + 32 * s);
                mma16816(acc[nt], ahi[s], bl);   // hi*lo
            }
        }

        // ---- banded epilogue: dx = j - x in [0,8] -> masked STG ----
        const int rbr = lane >> 2, cb = 2 * (lane & 3);
#pragma unroll
        for (int nt = 0; nt < 3; nt++) {
            const int n0 = 16 * w + 8 * nt;
#pragma unroll
            for (int h = 0; h < 2; h++) {
                const int x = x0 + rbr + 8 * h;
                float* op = out + (((size_t)(b * HH + y)) * WW + x) * KD + 9 * dy;
#pragma unroll
                for (int e = 0; e < 2; e++) {
                    const int dx = n0 + cb + e - x;
                    if (dx >= 0 && dx <= 8) {
                        float v = acc[nt][2 * h + e] * inv;
                        v = v > 0.f ? v : 0.1f * v;
                        op[dx] = v;
                    }
                }
            }
        }
        __syncthreads();   // all ldsm reads of B done before next fill
    }
}

extern "C" void kernel_launch(void* const* d_in, const int* in_sizes, int n_in,
                              void* d_out, int out_size)
{
    const float* F1 = (const float*)d_in[0];
    const float* F2 = (const float*)d_in[1];
    float* out = (float*)d_out;

    cudaFuncSetAttribute(corr_mma_kernel, cudaFuncAttributeMaxDynamicSharedMemorySize, SMEM_BYTES);

    split_kernel<<<BB * HH, NTHREADS>>>(F2);            // F2 -> bf16 hi/lo scratch (once)

    dim3 grid(HH, BB);     // (y, b): y-adjacent CTAs reuse scratch rows in L2
    dim3 block(NTHREADS);
    corr_mma_kernel<<<grid, block, SMEM_BYTES>>>(F1, out);
}